// round 3
// baseline (speedup 1.0000x reference)
#include <cuda_runtime.h>
#include <cuda_fp16.h>
#include <cstdint>

#define NKP 8192
#define KF 256
#define TILES 64                 // 8192/128
#define CH 32                    // K elems per smem chunk
#define NCH (KF / CH)            // 8
#define ROWB 80                  // smem row stride bytes (64 data + 16 pad)
#define PLANEB (128 * ROWB)      // 10240 bytes per plane
#define STAGEB (4 * PLANEB)      // 40960 per stage (A0,A1,B0,B1)

// ---------------- device scratch ----------------
// split planes: [mat(2)][limb(2)][8192][256] half
__device__ __align__(16) __half g_half[(size_t)2 * 2 * NKP * KF];

struct __align__(16) Top2 { float v1; int i1; float v2; int i2; };
__device__ Top2 g_rowPart[(size_t)NKP * TILES];
__device__ Top2 g_colPart[(size_t)NKP * TILES];
__device__ int g_fwd_nn[NKP];
__device__ int g_fwd_ok[NKP];
__device__ int g_bck_nn[NKP];
__device__ int g_bck_ok[NKP];

// ---------------- helpers ----------------
__device__ __forceinline__ void t2_ins(float& v1, int& i1, float& v2, int& i2,
                                       float v, int i) {
    if (v > v1 || (v == v1 && i < i1)) { v2 = v1; i2 = i1; v1 = v; i1 = i; }
    else if (v > v2 || (v == v2 && i < i2)) { v2 = v; i2 = i; }
}

__device__ __forceinline__ void t2_merge_shfl(float& v1, int& i1, float& v2, int& i2,
                                              int delta) {
    float qv1 = __shfl_xor_sync(0xffffffffu, v1, delta);
    int   qi1 = __shfl_xor_sync(0xffffffffu, i1, delta);
    float qv2 = __shfl_xor_sync(0xffffffffu, v2, delta);
    int   qi2 = __shfl_xor_sync(0xffffffffu, i2, delta);
    t2_ins(v1, i1, v2, i2, qv1, qi1);
    t2_ins(v1, i1, v2, i2, qv2, qi2);
}

__device__ __forceinline__ void cp16(void* s, const void* g) {
    unsigned ss = (unsigned)__cvta_generic_to_shared(s);
    asm volatile("cp.async.cg.shared.global [%0], [%1], 16;" :: "r"(ss), "l"(g));
}

__device__ __forceinline__ void mma_f16(float* c, const uint32_t* a, const uint32_t* b) {
    asm volatile(
        "mma.sync.aligned.m16n8k16.row.col.f32.f16.f16.f32 "
        "{%0,%1,%2,%3},{%4,%5,%6,%7},{%8,%9},{%0,%1,%2,%3};"
        : "+f"(c[0]), "+f"(c[1]), "+f"(c[2]), "+f"(c[3])
        : "r"(a[0]), "r"(a[1]), "r"(a[2]), "r"(a[3]), "r"(b[0]), "r"(b[1]));
}

// ---------------- split: fp32 -> 2-limb fp16 (limb1 scaled by 2048) --------
__global__ void split_kernel(const float* __restrict__ src, int mat)
{
    int t = blockIdx.x * blockDim.x + threadIdx.x;
    int n = t & (NKP - 1);
    int kb = t >> 13;                 // 0..31
    if (kb >= KF / 8) return;
    int k0 = kb * 8;

    uint32_t w0[4], w1[4];
#pragma unroll
    for (int p = 0; p < 4; p++) {
        float a = src[(size_t)(k0 + 2 * p) * NKP + n];
        float b = src[(size_t)(k0 + 2 * p + 1) * NKP + n];
        __half a0 = __float2half_rn(a), b0 = __float2half_rn(b);
        float ra = (a - __half2float(a0)) * 2048.0f;
        float rb = (b - __half2float(b0)) * 2048.0f;
        __half a1 = __float2half_rn(ra), b1 = __float2half_rn(rb);
        __half2 p0 = __halves2half2(a0, b0);
        __half2 p1 = __halves2half2(a1, b1);
        w0[p] = *reinterpret_cast<uint32_t*>(&p0);
        w1[p] = *reinterpret_cast<uint32_t*>(&p1);
    }
    size_t base0 = ((size_t)(mat * 2 + 0) * NKP + n) * KF + k0;
    size_t base1 = ((size_t)(mat * 2 + 1) * NKP + n) * KF + k0;
    *(uint4*)(g_half + base0) = make_uint4(w0[0], w0[1], w0[2], w0[3]);
    *(uint4*)(g_half + base1) = make_uint4(w1[0], w1[1], w1[2], w1[3]);
}

// ---------------- GEMM (HMMA) + fused top-2 epilogue ----------------------
extern __shared__ __align__(16) char smem[];

__global__ void __launch_bounds__(256)
gemm_hmma()
{
    const int tid = threadIdx.x, wid = tid >> 5, lane = tid & 31;
    const int g = lane >> 2, t = lane & 3;
    const int bx = blockIdx.x;    // col tile (matrix B / descriptors1)
    const int by = blockIdx.y;    // row tile (matrix A / descriptors0)
    const int wmI = wid & 1, wnI = wid >> 1;
    const int wm = wmI * 64, wn = wnI * 32;

    float s0[4][4][4], s1[4][4][4];
#pragma unroll
    for (int i = 0; i < 4; i++)
#pragma unroll
        for (int j = 0; j < 4; j++)
#pragma unroll
            for (int q = 0; q < 4; q++) { s0[i][j][q] = 0.f; s1[i][j][q] = 0.f; }

    // prefetch lambda: one chunk (A0,A1,B0,B1 planes) into a stage
    auto prefetch = [&](int chunk, int stage) {
        char* sb = smem + stage * STAGEB;
#pragma unroll
        for (int i = 0; i < 8; i++) {
            int idx = tid + i * 256;          // 0..2047
            int plane = idx >> 9;             // 0..3
            int rem = idx & 511;
            int row = rem >> 2, seg = rem & 3;
            int mat = plane >> 1, limb = plane & 1;
            int mnBase = (mat ? bx : by) * 128;
            const __half* src = g_half +
                ((size_t)(mat * 2 + limb) * NKP + mnBase + row) * KF + chunk * CH + seg * 8;
            cp16(sb + plane * PLANEB + row * ROWB + seg * 16, src);
        }
        asm volatile("cp.async.commit_group;");
    };

    prefetch(0, 0);

    for (int c = 0; c < NCH; c++) {
        const int s = c & 1;
        __syncthreads();
        if (c + 1 < NCH) {
            prefetch(c + 1, s ^ 1);
            asm volatile("cp.async.wait_group 1;");
        } else {
            asm volatile("cp.async.wait_group 0;");
        }
        __syncthreads();

        const char* sA0 = smem + s * STAGEB;
        const char* sA1 = sA0 + PLANEB;
        const char* sB0 = sA1 + PLANEB;
        const char* sB1 = sB0 + PLANEB;

#pragma unroll
        for (int k16 = 0; k16 < 2; k16++) {
            const int cb = k16 * 32 + t * 4;
            uint32_t a[4][4], b0[4][2], b1[4][2];
#pragma unroll
            for (int mf = 0; mf < 4; mf++) {
                int rA = wm + mf * 16 + g;
                a[mf][0] = *(const uint32_t*)(sA0 + rA * ROWB + cb);
                a[mf][1] = *(const uint32_t*)(sA0 + (rA + 8) * ROWB + cb);
                a[mf][2] = *(const uint32_t*)(sA0 + rA * ROWB + cb + 16);
                a[mf][3] = *(const uint32_t*)(sA0 + (rA + 8) * ROWB + cb + 16);
            }
#pragma unroll
            for (int nf = 0; nf < 4; nf++) {
                int rB = wn + nf * 8 + g;
                b0[nf][0] = *(const uint32_t*)(sB0 + rB * ROWB + cb);
                b0[nf][1] = *(const uint32_t*)(sB0 + rB * ROWB + cb + 16);
                b1[nf][0] = *(const uint32_t*)(sB1 + rB * ROWB + cb);
                b1[nf][1] = *(const uint32_t*)(sB1 + rB * ROWB + cb + 16);
            }
#pragma unroll
            for (int mf = 0; mf < 4; mf++)
#pragma unroll
                for (int nf = 0; nf < 4; nf++)
                    mma_f16(s0[mf][nf], a[mf], b0[nf]);
#pragma unroll
            for (int mf = 0; mf < 4; mf++)
#pragma unroll
                for (int nf = 0; nf < 4; nf++)
                    mma_f16(s1[mf][nf], a[mf], b1[nf]);
            // reload a <- A1 limb
#pragma unroll
            for (int mf = 0; mf < 4; mf++) {
                int rA = wm + mf * 16 + g;
                a[mf][0] = *(const uint32_t*)(sA1 + rA * ROWB + cb);
                a[mf][1] = *(const uint32_t*)(sA1 + (rA + 8) * ROWB + cb);
                a[mf][2] = *(const uint32_t*)(sA1 + rA * ROWB + cb + 16);
                a[mf][3] = *(const uint32_t*)(sA1 + (rA + 8) * ROWB + cb + 16);
            }
#pragma unroll
            for (int mf = 0; mf < 4; mf++)
#pragma unroll
                for (int nf = 0; nf < 4; nf++)
                    mma_f16(s1[mf][nf], a[mf], b0[nf]);
        }
    }

    // combine: dot = S0 + S1/2048
#pragma unroll
    for (int mf = 0; mf < 4; mf++)
#pragma unroll
        for (int nf = 0; nf < 4; nf++)
#pragma unroll
            for (int q = 0; q < 4; q++)
                s0[mf][nf][q] = fmaf(s1[mf][nf][q], 1.0f / 2048.0f, s0[mf][nf][q]);

    __syncthreads();   // mainloop smem dead; reuse for partials
    Top2* part_row = (Top2*)smem;                 // [128][4]
    Top2* part_col = (Top2*)(smem + 128 * 4 * 16); // [128][2]

    // ---- row top-2 (8 row-slots per thread: mf x h) ----
    {
        float rv1[4][2], rv2[4][2]; int ri1[4][2], ri2[4][2];
#pragma unroll
        for (int mf = 0; mf < 4; mf++)
#pragma unroll
            for (int h = 0; h < 2; h++) {
                rv1[mf][h] = -1e30f; rv2[mf][h] = -1e30f;
                ri1[mf][h] = 0x7fffffff; ri2[mf][h] = 0x7fffffff;
            }
        const int colBase = bx * 128 + wn;
#pragma unroll
        for (int mf = 0; mf < 4; mf++)
#pragma unroll
            for (int nf = 0; nf < 4; nf++)
#pragma unroll
                for (int p = 0; p < 2; p++) {
                    int col = colBase + nf * 8 + t * 2 + p;
                    t2_ins(rv1[mf][0], ri1[mf][0], rv2[mf][0], ri2[mf][0],
                           s0[mf][nf][p], col);
                    t2_ins(rv1[mf][1], ri1[mf][1], rv2[mf][1], ri2[mf][1],
                           s0[mf][nf][p + 2], col);
                }
#pragma unroll
        for (int mf = 0; mf < 4; mf++)
#pragma unroll
            for (int h = 0; h < 2; h++) {
                t2_merge_shfl(rv1[mf][h], ri1[mf][h], rv2[mf][h], ri2[mf][h], 1);
                t2_merge_shfl(rv1[mf][h], ri1[mf][h], rv2[mf][h], ri2[mf][h], 2);
            }
        if (t == 0) {
#pragma unroll
            for (int mf = 0; mf < 4; mf++)
#pragma unroll
                for (int h = 0; h < 2; h++) {
                    int rin = wmI * 64 + mf * 16 + h * 8 + g;
                    Top2 o; o.v1 = rv1[mf][h]; o.i1 = ri1[mf][h];
                    o.v2 = rv2[mf][h]; o.i2 = ri2[mf][h];
                    part_row[rin * 4 + wnI] = o;
                }
        }
    }
    // ---- col top-2 (8 col-slots per thread: nf x p) ----
    {
        float cv1[4][2], cv2[4][2]; int ci1[4][2], ci2[4][2];
#pragma unroll
        for (int nf = 0; nf < 4; nf++)
#pragma unroll
            for (int p = 0; p < 2; p++) {
                cv1[nf][p] = -1e30f; cv2[nf][p] = -1e30f;
                ci1[nf][p] = 0x7fffffff; ci2[nf][p] = 0x7fffffff;
            }
        const int rowBase = by * 128 + wm;
#pragma unroll
        for (int nf = 0; nf < 4; nf++)
#pragma unroll
            for (int p = 0; p < 2; p++)
#pragma unroll
                for (int mf = 0; mf < 4; mf++)
#pragma unroll
                    for (int h = 0; h < 2; h++) {
                        int row = rowBase + mf * 16 + h * 8 + g;
                        t2_ins(cv1[nf][p], ci1[nf][p], cv2[nf][p], ci2[nf][p],
                               s0[mf][nf][p + 2 * h], row);
                    }
#pragma unroll
        for (int nf = 0; nf < 4; nf++)
#pragma unroll
            for (int p = 0; p < 2; p++) {
                t2_merge_shfl(cv1[nf][p], ci1[nf][p], cv2[nf][p], ci2[nf][p], 4);
                t2_merge_shfl(cv1[nf][p], ci1[nf][p], cv2[nf][p], ci2[nf][p], 8);
                t2_merge_shfl(cv1[nf][p], ci1[nf][p], cv2[nf][p], ci2[nf][p], 16);
            }
        if (g == 0) {
#pragma unroll
            for (int nf = 0; nf < 4; nf++)
#pragma unroll
                for (int p = 0; p < 2; p++) {
                    int cin = wnI * 32 + nf * 8 + t * 2 + p;
                    Top2 o; o.v1 = cv1[nf][p]; o.i1 = ci1[nf][p];
                    o.v2 = cv2[nf][p]; o.i2 = ci2[nf][p];
                    part_col[cin * 2 + wmI] = o;
                }
        }
    }
    __syncthreads();
    if (tid < 128) {
        // rows
        float v1 = -1e30f, v2 = -1e30f; int i1 = 0x7fffffff, i2 = 0x7fffffff;
#pragma unroll
        for (int w = 0; w < 4; w++) {
            Top2 q = part_row[tid * 4 + w];
            t2_ins(v1, i1, v2, i2, q.v1, q.i1);
            t2_ins(v1, i1, v2, i2, q.v2, q.i2);
        }
        Top2 o; o.v1 = v1; o.i1 = i1; o.v2 = v2; o.i2 = i2;
        g_rowPart[(size_t)(by * 128 + tid) * TILES + bx] = o;
    } else {
        int col = tid - 128;
        float v1 = -1e30f, v2 = -1e30f; int i1 = 0x7fffffff, i2 = 0x7fffffff;
#pragma unroll
        for (int w = 0; w < 2; w++) {
            Top2 q = part_col[col * 2 + w];
            t2_ins(v1, i1, v2, i2, q.v1, q.i1);
            t2_ins(v1, i1, v2, i2, q.v2, q.i2);
        }
        Top2 o; o.v1 = v1; o.i1 = i1; o.v2 = v2; o.i2 = i2;
        g_colPart[(size_t)(bx * 128 + col) * TILES + by] = o;
    }
}

// ---------------- final reductions ----------------
__global__ void reduce_top2(int which, int tiles, int n)
{
    const Top2* part = which ? g_colPart : g_rowPart;
    int* nn = which ? g_bck_nn : g_fwd_nn;
    int* ok = which ? g_bck_ok : g_fwd_ok;

    int warp = (blockIdx.x * blockDim.x + threadIdx.x) >> 5;
    int lane = threadIdx.x & 31;
    if (warp >= n) return;

    float v1 = -1e30f, v2 = -1e30f; int i1 = 0x7fffffff, i2 = 0x7fffffff;
    for (int p = lane; p < tiles; p += 32) {
        Top2 q = part[(size_t)warp * tiles + p];
        t2_ins(v1, i1, v2, i2, q.v1, q.i1);
        t2_ins(v1, i1, v2, i2, q.v2, q.i2);
    }
    for (int off = 16; off > 0; off >>= 1)
        t2_merge_shfl(v1, i1, v2, i2, off);
    if (lane == 0) {
        float c1 = fmaxf(1.0f - v1, 1e-6f);
        float c2 = fmaxf(1.0f - v2, 1e-6f);
        nn[warp] = i1;
        ok[warp] = (c1 < c2) ? 1 : 0;
    }
}

__global__ void finalize(float* __restrict__ out, int n, int out_size)
{
    int e = blockIdx.x * blockDim.x + threadIdx.x;
    if (e >= out_size) return;
    int seg = e / n, i = e - seg * n;
    float val = 0.0f;
    if (seg == 0 || seg == 2) {
        int j = g_fwd_nn[i];
        bool mutual = g_fwd_ok[i] && g_bck_ok[j] && (g_bck_nn[j] == i);
        int idx = mutual ? j : -1;
        val = (seg == 0) ? (float)idx : ((idx > 0) ? 1.0f : 0.0f);
    } else if (seg == 1) {
        val = -1.0f;
    }
    out[e] = val;
}

extern "C" void kernel_launch(void* const* d_in, const int* in_sizes, int n_in,
                              void* d_out, int out_size)
{
    const float* d0 = (const float*)d_in[0];   // [K, N]
    const float* d1 = (const float*)d_in[1];   // [K, M]
    int N = in_sizes[2] / 2;
    int M = in_sizes[3] / 2;

    cudaFuncSetAttribute(gemm_hmma, cudaFuncAttributeMaxDynamicSharedMemorySize,
                         2 * STAGEB);

    int splitThreads = NKP * (KF / 8);
    split_kernel<<<splitThreads / 256, 256>>>(d0, 0);
    split_kernel<<<splitThreads / 256, 256>>>(d1, 1);

    dim3 grid(TILES, TILES);
    gemm_hmma<<<grid, 256, 2 * STAGEB>>>();

    reduce_top2<<<(N * 32 + 255) / 256, 256>>>(0, TILES, N);
    reduce_top2<<<(M * 32 + 255) / 256, 256>>>(1, TILES, M);

    finalize<<<(out_size + 255) / 256, 256>>>((float*)d_out, N, out_size);
}

// round 4
// speedup vs baseline: 1.6000x; 1.6000x over previous
#include <cuda_runtime.h>
#include <cuda_fp16.h>
#include <cstdint>

#define NKP 8192
#define KF 256
#define TILES 64                 // 8192/128
#define NCHUNK 12                // 3 product pairs x 4 chunks of K=64
#define STAGEB 32768             // (128+128) rows x 128 B

// ---------------- device scratch ----------------
// per matrix: [8192][512] half = [limb0(256) | limb1(256)], prescaled x256
__device__ __align__(16) __half g_A[(size_t)NKP * 512];
__device__ __align__(16) __half g_B[(size_t)NKP * 512];

struct __align__(16) Top2 { float v1; int i1; float v2; int i2; };
__device__ Top2 g_rowPart[(size_t)NKP * TILES];
__device__ Top2 g_colPart[(size_t)NKP * TILES];
__device__ int g_fwd_nn[NKP];
__device__ int g_fwd_ok[NKP];
__device__ int g_bck_nn[NKP];
__device__ int g_bck_ok[NKP];

// ---------------- helpers ----------------
__device__ __forceinline__ void t2_ins(float& v1, int& i1, float& v2, int& i2,
                                       float v, int i) {
    if (v > v1 || (v == v1 && i < i1)) { v2 = v1; i2 = i1; v1 = v; i1 = i; }
    else if (v > v2 || (v == v2 && i < i2)) { v2 = v; i2 = i; }
}

__device__ __forceinline__ void t2_merge_shfl(float& v1, int& i1, float& v2, int& i2,
                                              int delta) {
    float qv1 = __shfl_xor_sync(0xffffffffu, v1, delta);
    int   qi1 = __shfl_xor_sync(0xffffffffu, i1, delta);
    float qv2 = __shfl_xor_sync(0xffffffffu, v2, delta);
    int   qi2 = __shfl_xor_sync(0xffffffffu, i2, delta);
    t2_ins(v1, i1, v2, i2, qv1, qi1);
    t2_ins(v1, i1, v2, i2, qv2, qi2);
}

__device__ __forceinline__ void cp16(void* s, const void* g) {
    unsigned ss = (unsigned)__cvta_generic_to_shared(s);
    asm volatile("cp.async.cg.shared.global [%0], [%1], 16;" :: "r"(ss), "l"(g));
}

__device__ __forceinline__ void mma_f16(float* c, const uint32_t* a, const uint32_t* b) {
    asm volatile(
        "mma.sync.aligned.m16n8k16.row.col.f32.f16.f16.f32 "
        "{%0,%1,%2,%3},{%4,%5,%6,%7},{%8,%9},{%0,%1,%2,%3};"
        : "+f"(c[0]), "+f"(c[1]), "+f"(c[2]), "+f"(c[3])
        : "r"(a[0]), "r"(a[1]), "r"(a[2]), "r"(a[3]), "r"(b[0]), "r"(b[1]));
}

__device__ __forceinline__ void ldsm4(uint32_t& r0, uint32_t& r1,
                                      uint32_t& r2, uint32_t& r3, uint32_t addr) {
    asm volatile("ldmatrix.sync.aligned.m8n8.x4.shared.b16 {%0,%1,%2,%3},[%4];"
                 : "=r"(r0), "=r"(r1), "=r"(r2), "=r"(r3) : "r"(addr));
}

__device__ __forceinline__ uint32_t smem_u32(const void* p) {
    return (uint32_t)__cvta_generic_to_shared(p);
}

// ---------------- split: fp32 -> prescaled 2-limb fp16 --------------------
__global__ void split_kernel(const float* __restrict__ src, int mat)
{
    __half* __restrict__ dst = mat ? g_B : g_A;
    int t = blockIdx.x * blockDim.x + threadIdx.x;
    int n = t & (NKP - 1);
    int kb = t >> 13;                 // 0..31
    if (kb >= KF / 8) return;
    int k0 = kb * 8;

    uint32_t w0[4], w1[4];
#pragma unroll
    for (int p = 0; p < 4; p++) {
        float a = src[(size_t)(k0 + 2 * p) * NKP + n] * 256.0f;
        float b = src[(size_t)(k0 + 2 * p + 1) * NKP + n] * 256.0f;
        __half a0 = __float2half_rn(a), b0 = __float2half_rn(b);
        __half a1 = __float2half_rn(a - __half2float(a0));
        __half b1 = __float2half_rn(b - __half2float(b0));
        __half2 p0 = __halves2half2(a0, b0);
        __half2 p1 = __halves2half2(a1, b1);
        w0[p] = *reinterpret_cast<uint32_t*>(&p0);
        w1[p] = *reinterpret_cast<uint32_t*>(&p1);
    }
    *(uint4*)(dst + (size_t)n * 512 + k0)       = make_uint4(w0[0], w0[1], w0[2], w0[3]);
    *(uint4*)(dst + (size_t)n * 512 + 256 + k0) = make_uint4(w1[0], w1[1], w1[2], w1[3]);
}

// ---------------- GEMM (HMMA + ldmatrix) + fused top-2 epilogue -----------
extern __shared__ __align__(1024) char smem[];

__global__ void __launch_bounds__(256, 2)
gemm_hmma()
{
    const int tid = threadIdx.x, wid = tid >> 5, lane = tid & 31;
    const int g = lane >> 2, t = lane & 3;
    const int bx = blockIdx.x;    // col tile (B / descriptors1)
    const int by = blockIdx.y;    // row tile (A / descriptors0)
    const int wmI = wid & 1, wnI = wid >> 1;
    const int wm = wmI * 64, wn = wnI * 32;

    float s0[4][4][4];
#pragma unroll
    for (int i = 0; i < 4; i++)
#pragma unroll
        for (int j = 0; j < 4; j++)
#pragma unroll
            for (int q = 0; q < 4; q++) s0[i][j][q] = 0.f;

    // product pairs: (A limb, B limb) = (0,0), (0,1), (1,0); K=64 chunks x4 each
    auto prefetch = [&](int q, int stage) {
        int pair = q >> 2, c = q & 3;
        int aOff = (pair == 2) ? 256 : 0;
        int bOff = (pair == 1) ? 256 : 0;
        char* sb = smem + stage * STAGEB;
#pragma unroll
        for (int j = 0; j < 8; j++) {
            int idx = tid + j * 256;       // 0..2047
            int mat = idx >> 10;           // const per j
            int rem = idx & 1023;
            int row = rem >> 3, u = rem & 7;
            const __half* src = mat
                ? g_B + ((size_t)(bx * 128 + row)) * 512 + bOff + c * 64 + u * 8
                : g_A + ((size_t)(by * 128 + row)) * 512 + aOff + c * 64 + u * 8;
            cp16(sb + mat * 16384 + row * 128 + ((u ^ (row & 7)) << 4), src);
        }
        asm volatile("cp.async.commit_group;");
    };

    // per-lane ldmatrix geometry
    const int sub = lane >> 3;
    const int rowoff = (lane & 7) + (sub & 1) * 8;
    const int s2 = sub >> 1;            // k-unit select within k16
    int aRow[4], bRow[2];
#pragma unroll
    for (int mf = 0; mf < 4; mf++) aRow[mf] = wm + mf * 16 + rowoff;
#pragma unroll
    for (int p = 0; p < 2; p++) bRow[p] = wn + p * 16 + rowoff;

    const uint32_t sbu = smem_u32(smem);

    prefetch(0, 0);

    for (int q = 0; q < NCHUNK; q++) {
        const int s = q & 1;
        __syncthreads();
        if (q + 1 < NCHUNK) {
            prefetch(q + 1, s ^ 1);
            asm volatile("cp.async.wait_group 1;");
        } else {
            asm volatile("cp.async.wait_group 0;");
        }
        __syncthreads();

        const uint32_t sA_u = sbu + s * STAGEB;
        const uint32_t sB_u = sA_u + 16384;

#pragma unroll
        for (int k16 = 0; k16 < 4; k16++) {
            const int ku = k16 * 2 + s2;
            uint32_t a[4][4], b[4][2];
#pragma unroll
            for (int mf = 0; mf < 4; mf++) {
                int r = aRow[mf];
                ldsm4(a[mf][0], a[mf][1], a[mf][2], a[mf][3],
                      sA_u + r * 128 + ((ku ^ (r & 7)) << 4));
            }
#pragma unroll
            for (int p = 0; p < 2; p++) {
                int r = bRow[p];
                uint32_t r0, r1, r2, r3;
                ldsm4(r0, r1, r2, r3, sB_u + r * 128 + ((ku ^ (r & 7)) << 4));
                b[2 * p][0] = r0; b[2 * p + 1][0] = r1;
                b[2 * p][1] = r2; b[2 * p + 1][1] = r3;
            }
#pragma unroll
            for (int mf = 0; mf < 4; mf++)
#pragma unroll
                for (int nf = 0; nf < 4; nf++)
                    mma_f16(s0[mf][nf], a[mf], b[nf]);
        }
    }

    // undo the x256*x256 prescale
#pragma unroll
    for (int mf = 0; mf < 4; mf++)
#pragma unroll
        for (int nf = 0; nf < 4; nf++)
#pragma unroll
            for (int qq = 0; qq < 4; qq++)
                s0[mf][nf][qq] *= (1.0f / 65536.0f);

    __syncthreads();   // mainloop smem dead; reuse for partials
    Top2* part_row = (Top2*)smem;                   // [128][4]
    Top2* part_col = (Top2*)(smem + 128 * 4 * 16);  // [128][2]

    // ---- row top-2 ----
    {
        float rv1[4][2], rv2[4][2]; int ri1[4][2], ri2[4][2];
#pragma unroll
        for (int mf = 0; mf < 4; mf++)
#pragma unroll
            for (int h = 0; h < 2; h++) {
                rv1[mf][h] = -1e30f; rv2[mf][h] = -1e30f;
                ri1[mf][h] = 0x7fffffff; ri2[mf][h] = 0x7fffffff;
            }
        const int colBase = bx * 128 + wn;
#pragma unroll
        for (int mf = 0; mf < 4; mf++)
#pragma unroll
            for (int nf = 0; nf < 4; nf++)
#pragma unroll
                for (int p = 0; p < 2; p++) {
                    int col = colBase + nf * 8 + t * 2 + p;
                    t2_ins(rv1[mf][0], ri1[mf][0], rv2[mf][0], ri2[mf][0],
                           s0[mf][nf][p], col);
                    t2_ins(rv1[mf][1], ri1[mf][1], rv2[mf][1], ri2[mf][1],
                           s0[mf][nf][p + 2], col);
                }
#pragma unroll
        for (int mf = 0; mf < 4; mf++)
#pragma unroll
            for (int h = 0; h < 2; h++) {
                t2_merge_shfl(rv1[mf][h], ri1[mf][h], rv2[mf][h], ri2[mf][h], 1);
                t2_merge_shfl(rv1[mf][h], ri1[mf][h], rv2[mf][h], ri2[mf][h], 2);
            }
        if (t == 0) {
#pragma unroll
            for (int mf = 0; mf < 4; mf++)
#pragma unroll
                for (int h = 0; h < 2; h++) {
                    int rin = wmI * 64 + mf * 16 + h * 8 + g;
                    Top2 o; o.v1 = rv1[mf][h]; o.i1 = ri1[mf][h];
                    o.v2 = rv2[mf][h]; o.i2 = ri2[mf][h];
                    part_row[rin * 4 + wnI] = o;
                }
        }
    }
    // ---- col top-2 ----
    {
        float cv1[4][2], cv2[4][2]; int ci1[4][2], ci2[4][2];
#pragma unroll
        for (int nf = 0; nf < 4; nf++)
#pragma unroll
            for (int p = 0; p < 2; p++) {
                cv1[nf][p] = -1e30f; cv2[nf][p] = -1e30f;
                ci1[nf][p] = 0x7fffffff; ci2[nf][p] = 0x7fffffff;
            }
        const int rowBase = by * 128 + wm;
#pragma unroll
        for (int nf = 0; nf < 4; nf++)
#pragma unroll
            for (int p = 0; p < 2; p++)
#pragma unroll
                for (int mf = 0; mf < 4; mf++)
#pragma unroll
                    for (int h = 0; h < 2; h++) {
                        int row = rowBase + mf * 16 + h * 8 + g;
                        t2_ins(cv1[nf][p], ci1[nf][p], cv2[nf][p], ci2[nf][p],
                               s0[mf][nf][p + 2 * h], row);
                    }
#pragma unroll
        for (int nf = 0; nf < 4; nf++)
#pragma unroll
            for (int p = 0; p < 2; p++) {
                t2_merge_shfl(cv1[nf][p], ci1[nf][p], cv2[nf][p], ci2[nf][p], 4);
                t2_merge_shfl(cv1[nf][p], ci1[nf][p], cv2[nf][p], ci2[nf][p], 8);
                t2_merge_shfl(cv1[nf][p], ci1[nf][p], cv2[nf][p], ci2[nf][p], 16);
            }
        if (g == 0) {
#pragma unroll
            for (int nf = 0; nf < 4; nf++)
#pragma unroll
                for (int p = 0; p < 2; p++) {
                    int cin = wnI * 32 + nf * 8 + t * 2 + p;
                    Top2 o; o.v1 = cv1[nf][p]; o.i1 = ci1[nf][p];
                    o.v2 = cv2[nf][p]; o.i2 = ci2[nf][p];
                    part_col[cin * 2 + wmI] = o;
                }
        }
    }
    __syncthreads();
    if (tid < 128) {
        float v1 = -1e30f, v2 = -1e30f; int i1 = 0x7fffffff, i2 = 0x7fffffff;
#pragma unroll
        for (int w = 0; w < 4; w++) {
            Top2 q = part_row[tid * 4 + w];
            t2_ins(v1, i1, v2, i2, q.v1, q.i1);
            t2_ins(v1, i1, v2, i2, q.v2, q.i2);
        }
        Top2 o; o.v1 = v1; o.i1 = i1; o.v2 = v2; o.i2 = i2;
        g_rowPart[(size_t)(by * 128 + tid) * TILES + bx] = o;
    } else {
        int col = tid - 128;
        float v1 = -1e30f, v2 = -1e30f; int i1 = 0x7fffffff, i2 = 0x7fffffff;
#pragma unroll
        for (int w = 0; w < 2; w++) {
            Top2 q = part_col[col * 2 + w];
            t2_ins(v1, i1, v2, i2, q.v1, q.i1);
            t2_ins(v1, i1, v2, i2, q.v2, q.i2);
        }
        Top2 o; o.v1 = v1; o.i1 = i1; o.v2 = v2; o.i2 = i2;
        g_colPart[(size_t)(bx * 128 + col) * TILES + by] = o;
    }
}

// ---------------- final reductions ----------------
__global__ void reduce_top2(int which, int tiles, int n)
{
    const Top2* part = which ? g_colPart : g_rowPart;
    int* nn = which ? g_bck_nn : g_fwd_nn;
    int* ok = which ? g_bck_ok : g_fwd_ok;

    int warp = (blockIdx.x * blockDim.x + threadIdx.x) >> 5;
    int lane = threadIdx.x & 31;
    if (warp >= n) return;

    float v1 = -1e30f, v2 = -1e30f; int i1 = 0x7fffffff, i2 = 0x7fffffff;
    for (int p = lane; p < tiles; p += 32) {
        Top2 q = part[(size_t)warp * tiles + p];
        t2_ins(v1, i1, v2, i2, q.v1, q.i1);
        t2_ins(v1, i1, v2, i2, q.v2, q.i2);
    }
    for (int off = 16; off > 0; off >>= 1)
        t2_merge_shfl(v1, i1, v2, i2, off);
    if (lane == 0) {
        float c1 = fmaxf(1.0f - v1, 1e-6f);
        float c2 = fmaxf(1.0f - v2, 1e-6f);
        nn[warp] = i1;
        ok[warp] = (c1 < c2) ? 1 : 0;
    }
}

__global__ void finalize(float* __restrict__ out, int n, int out_size)
{
    int e = blockIdx.x * blockDim.x + threadIdx.x;
    if (e >= out_size) return;
    int seg = e / n, i = e - seg * n;
    float val = 0.0f;
    if (seg == 0 || seg == 2) {
        int j = g_fwd_nn[i];
        bool mutual = g_fwd_ok[i] && g_bck_ok[j] && (g_bck_nn[j] == i);
        int idx = mutual ? j : -1;
        val = (seg == 0) ? (float)idx : ((idx > 0) ? 1.0f : 0.0f);
    } else if (seg == 1) {
        val = -1.0f;
    }
    out[e] = val;
}

extern "C" void kernel_launch(void* const* d_in, const int* in_sizes, int n_in,
                              void* d_out, int out_size)
{
    const float* d0 = (const float*)d_in[0];   // [K, N]
    const float* d1 = (const float*)d_in[1];   // [K, M]
    int N = in_sizes[2] / 2;
    int M = in_sizes[3] / 2;

    cudaFuncSetAttribute(gemm_hmma, cudaFuncAttributeMaxDynamicSharedMemorySize,
                         2 * STAGEB);

    int splitThreads = NKP * (KF / 8);
    split_kernel<<<splitThreads / 256, 256>>>(d0, 0);
    split_kernel<<<splitThreads / 256, 256>>>(d1, 1);

    dim3 grid(TILES, TILES);
    gemm_hmma<<<grid, 256, 2 * STAGEB>>>();

    reduce_top2<<<(N * 32 + 255) / 256, 256>>>(0, TILES, N);
    reduce_top2<<<(M * 32 + 255) / 256, 256>>>(1, TILES, M);

    finalize<<<(out_size + 255) / 256, 256>>>((float*)d_out, N, out_size);
}